// round 11
// baseline (speedup 1.0000x reference)
#include <cuda_runtime.h>
#include <cuda_bf16.h>
typedef unsigned u32; typedef unsigned long long u64; typedef unsigned short u16;
#define NBLK 128
#define NTHR 256
#define TT 1024
#define HH 512

// packed h: low 16 = hi bf16, high 16 = lo bf16
__device__ __align__(16) u32 g_h1[2][128 * HH];
__device__ __align__(16) u32 g_h2[128 * HH];
__device__ float g_xt[TT * 128];
__device__ u32 g_cnt, g_epoch, g_dead;

// smem byte offsets
#define O_W1H 0          // each weight tile: 16 rows x 512 bf16, stride 1040B; lo at +WLO
#define O_H2H 33280
#define O_I2H 66560
#define O_STG 99840      // 2 slots x (hi 18432 + lo 18432), row stride 144B
#define O_G   173568     // gates exchange: 16 x 132 f32
#define O_WX  182016
#define O_BB1 182080
#define O_BB2 182144
#define O_RED 182208
#define SMEMSZ 183296
#define WLO 16640
#define SLO 18432

__device__ __forceinline__ float sigf(float v){ return __fdividef(1.f, 1.f + __expf(-v)); }
__device__ __forceinline__ u32 s2u(const void* p){ u32 a; asm("{.reg .u64 t;cvta.to.shared.u64 t,%1;cvt.u32.u64 %0,t;}":"=r"(a):"l"(p)); return a; }
__device__ __forceinline__ uint2 ldcg64(const void* p){ uint2 v; asm volatile("ld.global.cg.v2.u32 {%0,%1},[%2];":"=r"(v.x),"=r"(v.y):"l"(p)); return v; }
__device__ __forceinline__ u32 ldcg32(const void* p){ u32 v; asm volatile("ld.global.cg.u32 %0,[%1];":"=r"(v):"l"(p)); return v; }
__device__ __forceinline__ float bfv(u32 b){ u16 s=(u16)b; __nv_bfloat16 h=*(__nv_bfloat16*)&s; return __bfloat162float(h); }
__device__ __forceinline__ u16 tob(float f){ __nv_bfloat16 h=__float2bfloat16(f); return *(u16*)&h; }
__device__ __forceinline__ void ldm4(u32* r, u32 a){
  asm volatile("ldmatrix.sync.aligned.m8n8.x4.shared.b16 {%0,%1,%2,%3},[%4];"
    :"=r"(r[0]),"=r"(r[1]),"=r"(r[2]),"=r"(r[3]):"r"(a)); }
__device__ __forceinline__ void ldm2(u32* r, u32 a){
  asm volatile("ldmatrix.sync.aligned.m8n8.x2.shared.b16 {%0,%1},[%2];"
    :"=r"(r[0]),"=r"(r[1]):"r"(a)); }
__device__ __forceinline__ void mma16816(float* c, const u32* a, const u32* b){
  asm volatile("mma.sync.aligned.m16n8k16.row.col.f32.bf16.bf16.f32 "
    "{%0,%1,%2,%3},{%4,%5,%6,%7},{%8,%9},{%0,%1,%2,%3};"
    :"+f"(c[0]),"+f"(c[1]),"+f"(c[2]),"+f"(c[3])
    :"r"(a[0]),"r"(a[1]),"r"(a[2]),"r"(a[3]),"r"(b[0]),"r"(b[1])); }

// grid barrier with deadlock poison: a stuck barrier terminates instead of hanging
__device__ __forceinline__ void gridbar(){
  __syncthreads();
  if(threadIdx.x==0){
    u32 dead; asm volatile("ld.relaxed.gpu.u32 %0,[%1];":"=r"(dead):"l"(&g_dead));
    if(!dead){
      u32 e; asm volatile("ld.acquire.gpu.u32 %0,[%1];":"=r"(e):"l"(&g_epoch));
      u32 r; asm volatile("atom.add.release.gpu.u32 %0,[%1],%2;":"=r"(r):"l"(&g_cnt),"r"(1u));
      if(r==NBLK-1){
        asm volatile("st.relaxed.gpu.u32 [%0],%1;"::"l"(&g_cnt),"r"(0u));
        asm volatile("red.release.gpu.add.u32 [%0],%1;"::"l"(&g_epoch),"r"(1u));
      } else {
        u32 c, it=0;
        do{
          asm volatile("ld.acquire.gpu.u32 %0,[%1];":"=r"(c):"l"(&g_epoch));
          if(c!=e) break;
          asm volatile("ld.relaxed.gpu.u32 %0,[%1];":"=r"(dead):"l"(&g_dead));
          if(dead) break;
          if(++it > 20000000u){ atomicExch(&g_dead,1u); break; }
        } while(1);
      }
    }
  }
  __syncthreads();
}

// stage: load 16 uint2 (32 packed k) per thread for chunk c of one h matrix
__device__ __forceinline__ void stg_ld(uint2 v[16], const u32* src, int c, int tid){
  const u32* p = src + (tid>>1)*HH + c*64 + (tid&1)*32;
#pragma unroll
  for(int j=0;j<16;j++) v[j] = ldcg64(p + j*2);
}
// split packed regs into hi/lo bf16 stage buffers
__device__ __forceinline__ void stg_st(const uint2 v[16], char* bhi, int tid){
  char* d = bhi + (tid>>1)*144 + (tid&1)*64;
#pragma unroll
  for(int j=0;j<8;j++){
    u32 h01=__byte_perm(v[2*j].x,v[2*j].y,0x5410), h23=__byte_perm(v[2*j+1].x,v[2*j+1].y,0x5410);
    u32 l01=__byte_perm(v[2*j].x,v[2*j].y,0x7632), l23=__byte_perm(v[2*j+1].x,v[2*j+1].y,0x7632);
    *(uint2*)(d + j*8)       = make_uint2(h01,h23);
    *(uint2*)(d + SLO + j*8) = make_uint2(l01,l23);
  }
}
// MMAs for one 64-k chunk: 3 split passes, 2 n-tiles
__device__ __forceinline__ void gemm_chunk(u32 smb, int wbase, u32 bufhi, int c,
                                           int lane, int warp, float C[2][4]){
  const int krow = lane & 15, ko = (lane>>4)*8;
  const int l16 = lane & 15, nr = l16 & 7, ko2 = (l16>>3)*8;
#pragma unroll
  for(int kt=0;kt<4;kt++){
    u32 ah[4], al[4];
    u32 aa = smb + (u32)wbase + (u32)krow*1040u + (u32)((c*64 + kt*16 + ko)*2);
    ldm4(ah, aa); ldm4(al, aa + WLO);
#pragma unroll
    for(int nt=0;nt<2;nt++){
      u32 ba = bufhi + (u32)((warp*16 + nt*8 + nr)*144) + (u32)((kt*16 + ko2)*2);
      u32 bh[2], bl[2]; ldm2(bh, ba); ldm2(bl, ba + SLO);
      mma16816(C[nt], ah, bh);
      mma16816(C[nt], ah, bl);
      mma16816(C[nt], al, bh);
    }
  }
}
// full 512-k GEMM of one h matrix with register-prefetch pipelining
__device__ __forceinline__ void gemm_full(u32 smb, char* sm, const u32* hsrc, int wbase,
                                          float C[2][4], int tid, int lane, int warp){
  uint2 v[16];
  stg_ld(v, hsrc, 0, tid);
#pragma unroll 1
  for(int c=0;c<8;c++){
    int slot = c & 1;
    stg_st(v, sm + O_STG + slot*2*SLO, tid);
    __syncthreads();
    if(c<7) stg_ld(v, hsrc, c+1, tid);
    gemm_chunk(smb, wbase, smb + O_STG + (u32)(slot*2*SLO), c, lane, warp, C);
    __syncthreads();
  }
}

__global__ void __launch_bounds__(NTHR,1)
lstm_mma(const float* __restrict__ x, const float* __restrict__ Wih1, const float* __restrict__ Whh1,
         const float* __restrict__ bih1, const float* __restrict__ bhh1,
         const float* __restrict__ Wih2, const float* __restrict__ Whh2,
         const float* __restrict__ bih2, const float* __restrict__ bhh2,
         const float* __restrict__ Wlin, const float* __restrict__ blin, float* __restrict__ out){
  extern __shared__ __align__(128) char sm[];
  const int tid=threadIdx.x, blk=blockIdx.x, warp=tid>>5, lane=tid&31;
  const u32 smb = s2u(sm);

  // x transpose (each block handles its 8 t-columns)
  for(int i=tid;i<1024;i+=NTHR){ int t=blk*8+(i>>7), b=i&127; g_xt[t*128+b]=x[b*TT+t]; }
  // weights -> smem bf16 hi/lo, row-major [16][512], stride 1040B
  { const float* WS[3]={Whh1,Whh2,Wih2}; const int WO[3]={O_W1H,O_H2H,O_I2H};
    for(int m=0;m<3;m++) for(int idx=tid; idx<16*HH; idx+=NTHR){
      int s=idx&15, k=idx>>4; int r=(s&3)*HH + blk*4 + (s>>2);
      float w=WS[m][r*HH+k]; u16 hb=tob(w); u16 lb=tob(w-bfv(hb));
      *(u16*)(sm+WO[m]+s*1040+k*2)=hb; *(u16*)(sm+WO[m]+WLO+s*1040+k*2)=lb; } }
  if(tid<16){ int s=tid, r=(s&3)*HH + blk*4 + (s>>2);
    ((float*)(sm+O_WX))[s]=Wih1[r];
    ((float*)(sm+O_BB1))[s]=bih1[r]+bhh1[r];
    ((float*)(sm+O_BB2))[s]=bih2[r]+bhh2[r]; }
  const float wl0=Wlin[tid*2], wl1=Wlin[tid*2+1], blinv=blin[0];
  for(int i=tid;i<512;i+=NTHR){ int b=i>>2, c=i&3;
    g_h1[0][b*HH+blk*4+c]=0; g_h2[b*HH+blk*4+c]=0; }
  __syncthreads();
  gridbar();

  float c1s[2]={0,0}, c2s[2]={0,0};

  for(int t=0;t<TT;t++){
    const u32* h1r = g_h1[t&1];
    u32*       h1w = g_h1[(t&1)^1];

    // out[t-1] partials (h2 stable since last gridbar)
    if(t>0){
      u32 p0=ldcg32(&g_h2[blk*HH+tid*2]), p1=ldcg32(&g_h2[blk*HH+tid*2+1]);
      ((float*)(sm+O_RED))[tid]=(bfv(p0)+bfv(p0>>16))*wl0+(bfv(p1)+bfv(p1>>16))*wl1;
    }

    float C1[2][4]={{0,0,0,0},{0,0,0,0}}, C2[2][4]={{0,0,0,0},{0,0,0,0}};
    gemm_full(smb, sm, h1r,  O_W1H, C1, tid, lane, warp);   // gates1 = Whh1*h1
    gemm_full(smb, sm, g_h2, O_H2H, C2, tid, lane, warp);   // gates2 += Whh2*h2

    // epilogue A: exchange C1 through smem
    { float* G=(float*)(sm+O_G);
#pragma unroll
      for(int nt=0;nt<2;nt++){ int n0=warp*16+nt*8+(lane&3)*2; int rr=lane>>2;
        *(float2*)&G[rr*132+n0]     = make_float2(C1[nt][0],C1[nt][1]);
        *(float2*)&G[(rr+8)*132+n0] = make_float2(C1[nt][2],C1[nt][3]); } }
    __syncthreads();
    if(t>0 && warp==7){ float* R=(float*)(sm+O_RED); float sv=0.f;
#pragma unroll
      for(int j=0;j<8;j++) sv+=R[lane+j*32];
      for(int o=16;o;o>>=1) sv+=__shfl_down_sync(~0u,sv,o);
      if(lane==0) out[blk*TT+t-1]=sv+blinv; }
    { float* G=(float*)(sm+O_G); float* WX=(float*)(sm+O_WX); float* B1=(float*)(sm+O_BB1);
#pragma unroll
      for(int i=0;i<2;i++){ int id=tid+256*i, b=id&127, cl=id>>7; int s0=cl*4;
        float xv=g_xt[t*128+b];
        float gi=G[(s0+0)*132+b]+B1[s0+0]+xv*WX[s0+0];
        float gf=G[(s0+1)*132+b]+B1[s0+1]+xv*WX[s0+1];
        float gg=G[(s0+2)*132+b]+B1[s0+2]+xv*WX[s0+2];
        float go=G[(s0+3)*132+b]+B1[s0+3]+xv*WX[s0+3];
        float cn=sigf(gf)*c1s[i]+sigf(gi)*tanhf(gg); c1s[i]=cn;
        float h=sigf(go)*tanhf(cn);
        u16 hb=tob(h); u16 lb=tob(h-bfv(hb));
        h1w[b*HH+blk*4+cl]=(u32)hb|((u32)lb<<16); } }
    gridbar();   // h1[t] visible everywhere

    // phase B: gates2 += Wih2 * h1_new
    gemm_full(smb, sm, h1w, O_I2H, C2, tid, lane, warp);

    { float* G=(float*)(sm+O_G);
#pragma unroll
      for(int nt=0;nt<2;nt++){ int n0=warp*16+nt*8+(lane&3)*2; int rr=lane>>2;
        *(float2*)&G[rr*132+n0]     = make_float2(C2[nt][0],C2[nt][1]);
        *(float2*)&G[(rr+8)*132+n0] = make_float2(C2[nt][2],C2[nt][3]); } }
    __syncthreads();
    { float* G=(float*)(sm+O_G); float* B2=(float*)(sm+O_BB2);
#pragma unroll
      for(int i=0;i<2;i++){ int id=tid+256*i, b=id&127, cl=id>>7; int s0=cl*4;
        float gi=G[(s0+0)*132+b]+B2[s0+0];
        float gf=G[(s0+1)*132+b]+B2[s0+1];
        float gg=G[(s0+2)*132+b]+B2[s0+2];
        float go=G[(s0+3)*132+b]+B2[s0+3];
        float cn=sigf(gf)*c2s[i]+sigf(gi)*tanhf(gg); c2s[i]=cn;
        float h=sigf(go)*tanhf(cn);
        u16 hb=tob(h); u16 lb=tob(h-bfv(hb));
        g_h2[b*HH+blk*4+cl]=(u32)hb|((u32)lb<<16); } }
    gridbar();   // h2[t] visible everywhere
  }

  // final out column
  { u32 p0=ldcg32(&g_h2[blk*HH+tid*2]), p1=ldcg32(&g_h2[blk*HH+tid*2+1]);
    ((float*)(sm+O_RED))[tid]=(bfv(p0)+bfv(p0>>16))*wl0+(bfv(p1)+bfv(p1>>16))*wl1;
    __syncthreads();
    if(warp==0){ float* R=(float*)(sm+O_RED); float sv=0.f;
#pragma unroll
      for(int j=0;j<8;j++) sv+=R[lane+j*32];
      for(int o=16;o;o>>=1) sv+=__shfl_down_sync(~0u,sv,o);
      if(lane==0) out[blk*TT+TT-1]=sv+blinv; } }
}

extern "C" void kernel_launch(void* const* d_in, const int* in_sizes, int n_in,
                              void* d_out, int out_size){
  const float* x   =(const float*)d_in[0];
  const float* Wih1=(const float*)d_in[1];
  const float* Whh1=(const float*)d_in[2];
  const float* bih1=(const float*)d_in[3];
  const float* bhh1=(const float*)d_in[4];
  const float* Wih2=(const float*)d_in[5];
  const float* Whh2=(const float*)d_in[6];
  const float* bih2=(const float*)d_in[7];
  const float* bhh2=(const float*)d_in[8];
  const float* Wlin=(const float*)d_in[9];
  const float* blin=(const float*)d_in[10];
  float* out=(float*)d_out;
  cudaFuncSetAttribute(lstm_mma, cudaFuncAttributeMaxDynamicSharedMemorySize, SMEMSZ);
  lstm_mma<<<NBLK,NTHR,SMEMSZ>>>(x,Wih1,Whh1,bih1,bhh1,Wih2,Whh2,bih2,bhh2,Wlin,blin,out);
}

// round 12
// speedup vs baseline: 4.0019x; 4.0019x over previous
#include <cuda_runtime.h>
#include <cuda_bf16.h>
typedef unsigned u32; typedef unsigned long long u64; typedef unsigned short u16;
#define NBLK 128
#define NTHR 256
#define TT 1024
#define HH 512

// packed h: low 16 = hi bf16, high 16 = lo bf16
__device__ __align__(16) u32 g_h1[2][128 * HH];
__device__ __align__(16) u32 g_h2[128 * HH];
__device__ float g_xt[TT * 128];
__device__ u32 g_cnt, g_epoch, g_dead;

// smem layout (bytes)
#define O_W1  0          // weight tile: hi 16x1024B, lo at +16384 (32KB per matrix)
#define O_H2  32768
#define O_I2  65536
#define O_STG 98304      // 2 slots x 32768 (hi 16KB + lo 16KB), rows 128B swizzled
#define O_G   163840     // gates exchange: 16 x 132 f32 = 8448
#define O_WX  172288
#define O_BB1 172352
#define O_BB2 172416
#define O_RED 172480     // 256 f32
#define SMEMSZ 173568

__device__ __forceinline__ float sigf(float v){ return __fdividef(1.f, 1.f + __expf(-v)); }
__device__ __forceinline__ u32 s2u(const void* p){ u32 a; asm("{.reg .u64 t;cvta.to.shared.u64 t,%1;cvt.u32.u64 %0,t;}":"=r"(a):"l"(p)); return a; }
__device__ __forceinline__ uint4 ldcg128(const void* p){ uint4 v; asm volatile("ld.global.cg.v4.u32 {%0,%1,%2,%3},[%4];":"=r"(v.x),"=r"(v.y),"=r"(v.z),"=r"(v.w):"l"(p)); return v; }
__device__ __forceinline__ u32 ldcg32(const void* p){ u32 v; asm volatile("ld.global.cg.u32 %0,[%1];":"=r"(v):"l"(p)); return v; }
__device__ __forceinline__ float bfv(u32 b){ u16 s=(u16)b; __nv_bfloat16 h=*(__nv_bfloat16*)&s; return __bfloat162float(h); }
__device__ __forceinline__ u16 tob(float f){ __nv_bfloat16 h=__float2bfloat16(f); return *(u16*)&h; }
__device__ __forceinline__ void ldm4(u32* r, u32 a){
  asm volatile("ldmatrix.sync.aligned.m8n8.x4.shared.b16 {%0,%1,%2,%3},[%4];"
    :"=r"(r[0]),"=r"(r[1]),"=r"(r[2]),"=r"(r[3]):"r"(a)); }
__device__ __forceinline__ void mma16816(float* c, const u32* a, const u32* b){
  asm volatile("mma.sync.aligned.m16n8k16.row.col.f32.bf16.bf16.f32 "
    "{%0,%1,%2,%3},{%4,%5,%6,%7},{%8,%9},{%0,%1,%2,%3};"
    :"+f"(c[0]),"+f"(c[1]),"+f"(c[2]),"+f"(c[3])
    :"r"(a[0]),"r"(a[1]),"r"(a[2]),"r"(a[3]),"r"(b[0]),"r"(b[1])); }

// grid barrier with deadlock poison (proven R11)
__device__ __forceinline__ void gridbar(){
  __syncthreads();
  if(threadIdx.x==0){
    u32 dead; asm volatile("ld.relaxed.gpu.u32 %0,[%1];":"=r"(dead):"l"(&g_dead));
    if(!dead){
      u32 e; asm volatile("ld.acquire.gpu.u32 %0,[%1];":"=r"(e):"l"(&g_epoch));
      u32 r; asm volatile("atom.add.release.gpu.u32 %0,[%1],%2;":"=r"(r):"l"(&g_cnt),"r"(1u));
      if(r==NBLK-1){
        asm volatile("st.relaxed.gpu.u32 [%0],%1;"::"l"(&g_cnt),"r"(0u));
        asm volatile("red.release.gpu.add.u32 [%0],%1;"::"l"(&g_epoch),"r"(1u));
      } else {
        u32 c, it=0;
        do{
          asm volatile("ld.acquire.gpu.u32 %0,[%1];":"=r"(c):"l"(&g_epoch));
          if(c!=e) break;
          asm volatile("ld.relaxed.gpu.u32 %0,[%1];":"=r"(dead):"l"(&g_dead));
          if(dead) break;
          if(++it > 20000000u){ atomicExch(&g_dead,1u); break; }
        } while(1);
      }
    }
  }
  __syncthreads();
}

// coalesced stage load: warp w covers rows w*16..w*16+15; 2 full 256B rows per instr
__device__ __forceinline__ void stg_ld(uint4 v[8], const u32* src, int c, int warp, int lane){
  const int rb = warp*16 + (lane>>4);
  const int l2 = lane&15;
#pragma unroll
  for(int j=0;j<8;j++){
    int R = rb + j*2;
    v[j] = ldcg128(src + R*HH + c*64 + l2*4);
  }
}
// split into swizzled hi/lo stage (rows 128B, atom16 ^= row&7) — conflict-free
__device__ __forceinline__ void stg_st(const uint4 v[8], char* buf, int warp, int lane){
  const int rb = warp*16 + (lane>>4);
  const int l2 = lane&15;
#pragma unroll
  for(int j=0;j<8;j++){
    int R = rb + j*2;
    u32 h0=__byte_perm(v[j].x,v[j].y,0x5410), h1=__byte_perm(v[j].z,v[j].w,0x5410);
    u32 l0=__byte_perm(v[j].x,v[j].y,0x7632), l1=__byte_perm(v[j].z,v[j].w,0x7632);
    u32 off = (u32)(R*128) + (u32)((((l2>>1)^(R&7))<<4)) + (u32)((l2&1)*8);
    *(uint2*)(buf + off)         = make_uint2(h0,h1);
    *(uint2*)(buf + 16384 + off) = make_uint2(l0,l1);
  }
}
// one 64-k chunk: 4 kt x (A hi/lo ldm4 + B hi/lo ldm4(2 n-tiles) + 6 mma)
__device__ __forceinline__ void gemm_chunk(u32 smb, int wbase, u32 stg, int c,
                                           int lane, int warp, float C[2][4]){
  const int krow = lane&15, khalf = lane>>4;
  const int brow = warp*16 + ((lane>>4)<<3) + (lane&7);
  const int bk   = (lane>>3)&1;
#pragma unroll
  for(int kt=0;kt<4;kt++){
    int aatom = c*8 + kt*2 + khalf;
    u32 aa = smb + (u32)wbase + (u32)(krow*1024) + (u32)(((aatom^(krow&7)))<<4);
    u32 ah[4], al[4]; ldm4(ah,aa); ldm4(al,aa+16384);
    int batom = kt*2 + bk;
    u32 ba = stg + (u32)(brow*128) + (u32)(((batom^(brow&7)))<<4);
    u32 bh[4], bl[4]; ldm4(bh,ba); ldm4(bl,ba+16384);
    mma16816(C[0],ah,bh);   mma16816(C[0],ah,bl);   mma16816(C[0],al,bh);
    mma16816(C[1],ah,bh+2); mma16816(C[1],ah,bl+2); mma16816(C[1],al,bh+2);
  }
}
// full 512-k GEMM: 2 slots, 1 sync per chunk, register prefetch
__device__ __forceinline__ void gemm_full(u32 smb, char* sm, const u32* hsrc, int wbase,
                                          float C[2][4], int lane, int warp){
  uint4 v[8];
  stg_ld(v, hsrc, 0, warp, lane);
#pragma unroll 1
  for(int c=0;c<8;c++){
    char* buf = sm + O_STG + (c&1)*32768;
    stg_st(v, buf, warp, lane);
    if(c<7) stg_ld(v, hsrc, c+1, warp, lane);
    __syncthreads();
    gemm_chunk(smb, wbase, smb + O_STG + (u32)((c&1)*32768), c, lane, warp, C);
  }
}

__global__ void __launch_bounds__(NTHR,1)
lstm_mma(const float* __restrict__ x, const float* __restrict__ Wih1, const float* __restrict__ Whh1,
         const float* __restrict__ bih1, const float* __restrict__ bhh1,
         const float* __restrict__ Wih2, const float* __restrict__ Whh2,
         const float* __restrict__ bih2, const float* __restrict__ bhh2,
         const float* __restrict__ Wlin, const float* __restrict__ blin, float* __restrict__ out){
  extern __shared__ __align__(128) char sm[];
  const int tid=threadIdx.x, blk=blockIdx.x, warp=tid>>5, lane=tid&31;
  const u32 smb = s2u(sm);

  // x transpose (each block its 8 t-columns)
  for(int i=tid;i<1024;i+=NTHR){ int t=blk*8+(i>>7), b=i&127; g_xt[t*128+b]=x[b*TT+t]; }
  // weights -> smem bf16 hi/lo, 1024B rows, swizzled atoms
  { const float* WS[3]={Whh1,Whh2,Wih2}; const int WO[3]={O_W1,O_H2,O_I2};
    for(int m=0;m<3;m++) for(int idx=tid; idx<16*HH; idx+=NTHR){
      int s=idx&15, k=idx>>4; int r=(s&3)*HH + blk*4 + (s>>2);
      float w=WS[m][r*HH+k]; u16 hb=tob(w); u16 lb=tob(w-bfv(hb));
      u32 off=(u32)(s*1024) + (u32)((((k>>3)^(s&7))<<4)) + (u32)((k&7)*2);
      *(u16*)(sm+WO[m]+off)=hb; *(u16*)(sm+WO[m]+16384+off)=lb; } }
  if(tid<16){ int s=tid, r=(s&3)*HH + blk*4 + (s>>2);
    ((float*)(sm+O_WX))[s]=Wih1[r];
    ((float*)(sm+O_BB1))[s]=bih1[r]+bhh1[r];
    ((float*)(sm+O_BB2))[s]=bih2[r]+bhh2[r]; }
  const float wl0=Wlin[tid*2], wl1=Wlin[tid*2+1], blinv=blin[0];
  for(int i=tid;i<512;i+=NTHR){ int b=i>>2, c=i&3;
    g_h1[0][b*HH+blk*4+c]=0; g_h2[b*HH+blk*4+c]=0; }
  __syncthreads();
  gridbar();

  float c1s[4]={0,0,0,0}, c2s[4]={0,0,0,0};   // cells: threads 0-127, batch=tid, 4 cols

  for(int t=0;t<TT;t++){
    const u32* h1r = g_h1[t&1];
    u32*       h1w = g_h1[(t&1)^1];

    // out[t-1] partials (h2 stable since last gridbar)
    if(t>0){
      u32 p0=ldcg32(&g_h2[blk*HH+tid*2]), p1=ldcg32(&g_h2[blk*HH+tid*2+1]);
      ((float*)(sm+O_RED))[tid]=(bfv(p0)+bfv(p0>>16))*wl0+(bfv(p1)+bfv(p1>>16))*wl1;
    }

    float C1[2][4]={{0,0,0,0},{0,0,0,0}}, C2[2][4]={{0,0,0,0},{0,0,0,0}};
    gemm_full(smb, sm, h1r,  O_W1, C1, lane, warp);   // gates1 = Whh1*h1
    gemm_full(smb, sm, g_h2, O_H2, C2, lane, warp);   // gates2  = Whh2*h2

    // epilogue A: exchange C1 -> G
    { float* G=(float*)(sm+O_G);
#pragma unroll
      for(int nt=0;nt<2;nt++){ int n0=warp*16+nt*8+(lane&3)*2; int rr=lane>>2;
        *(float2*)&G[rr*132+n0]     = make_float2(C1[nt][0],C1[nt][1]);
        *(float2*)&G[(rr+8)*132+n0] = make_float2(C1[nt][2],C1[nt][3]); } }
    __syncthreads();
    if(t>0 && warp==7){ float* R=(float*)(sm+O_RED); float sv=0.f;
#pragma unroll
      for(int j=0;j<8;j++) sv+=R[lane+j*32];
      for(int o=16;o;o>>=1) sv+=__shfl_down_sync(~0u,sv,o);
      if(lane==0) out[blk*TT+t-1]=sv+blinv; }
    if(tid<128){
      float* G=(float*)(sm+O_G); float* WX=(float*)(sm+O_WX); float* B1=(float*)(sm+O_BB1);
      int b=tid; float xv=g_xt[t*128+b];
      u32 hp[4];
#pragma unroll
      for(int cl=0;cl<4;cl++){ int s0=cl*4;
        float gi=G[(s0+0)*132+b]+B1[s0+0]+xv*WX[s0+0];
        float gf=G[(s0+1)*132+b]+B1[s0+1]+xv*WX[s0+1];
        float gg=G[(s0+2)*132+b]+B1[s0+2]+xv*WX[s0+2];
        float go=G[(s0+3)*132+b]+B1[s0+3]+xv*WX[s0+3];
        float cn=sigf(gf)*c1s[cl]+sigf(gi)*tanhf(gg); c1s[cl]=cn;
        float h=sigf(go)*tanhf(cn);
        u16 hb=tob(h); u16 lb=tob(h-bfv(hb));
        hp[cl]=(u32)hb|((u32)lb<<16); }
      *(uint4*)&h1w[b*HH+blk*4]=make_uint4(hp[0],hp[1],hp[2],hp[3]);
    }
    gridbar();   // h1[t] visible everywhere

    // phase B: gates2 += Wih2 * h1_new
    gemm_full(smb, sm, h1w, O_I2, C2, lane, warp);

    { float* G=(float*)(sm+O_G);
#pragma unroll
      for(int nt=0;nt<2;nt++){ int n0=warp*16+nt*8+(lane&3)*2; int rr=lane>>2;
        *(float2*)&G[rr*132+n0]     = make_float2(C2[nt][0],C2[nt][1]);
        *(float2*)&G[(rr+8)*132+n0] = make_float2(C2[nt][2],C2[nt][3]); } }
    __syncthreads();
    if(tid<128){
      float* G=(float*)(sm+O_G); float* B2=(float*)(sm+O_BB2);
      int b=tid;
      u32 hp[4];
#pragma unroll
      for(int cl=0;cl<4;cl++){ int s0=cl*4;
        float gi=G[(s0+0)*132+b]+B2[s0+0];
        float gf=G[(s0+1)*132+b]+B2[s0+1];
        float gg=G[(s0+2)*132+b]+B2[s0+2];
        float go=G[(s0+3)*132+b]+B2[s0+3];
        float cn=sigf(gf)*c2s[cl]+sigf(gi)*tanhf(gg); c2s[cl]=cn;
        float h=sigf(go)*tanhf(cn);
        u16 hb=tob(h); u16 lb=tob(h-bfv(hb));
        hp[cl]=(u32)hb|((u32)lb<<16); }
      *(uint4*)&g_h2[b*HH+blk*4]=make_uint4(hp[0],hp[1],hp[2],hp[3]);
    }
    gridbar();   // h2[t] visible everywhere
  }

  // final out column
  { u32 p0=ldcg32(&g_h2[blk*HH+tid*2]), p1=ldcg32(&g_h2[blk*HH+tid*2+1]);
    ((float*)(sm+O_RED))[tid]=(bfv(p0)+bfv(p0>>16))*wl0+(bfv(p1)+bfv(p1>>16))*wl1;
    __syncthreads();
    if(warp==0){ float* R=(float*)(sm+O_RED); float sv=0.f;
#pragma unroll
      for(int j=0;j<8;j++) sv+=R[lane+j*32];
      for(int o=16;o;o>>=1) sv+=__shfl_down_sync(~0u,sv,o);
      if(lane==0) out[blk*TT+TT-1]=sv+blinv; } }
}

extern "C" void kernel_launch(void* const* d_in, const int* in_sizes, int n_in,
                              void* d_out, int out_size){
  const float* x   =(const float*)d_in[0];
  const float* Wih1=(const float*)d_in[1];
  const float* Whh1=(const float*)d_in[2];
  const float* bih1=(const float*)d_in[3];
  const float* bhh1=(const float*)d_in[4];
  const float* Wih2=(const float*)d_in[5];
  const float* Whh2=(const float*)d_in[6];
  const float* bih2=(const float*)d_in[7];
  const float* bhh2=(const float*)d_in[8];
  const float* Wlin=(const float*)d_in[9];
  const float* blin=(const float*)d_in[10];
  float* out=(float*)d_out;
  cudaFuncSetAttribute(lstm_mma, cudaFuncAttributeMaxDynamicSharedMemorySize, SMEMSZ);
  lstm_mma<<<NBLK,NTHR,SMEMSZ>>>(x,Wih1,Whh1,bih1,bhh1,Wih2,Whh2,bih2,bhh2,Wlin,blin,out);
}

// round 13
// speedup vs baseline: 4.4752x; 1.1182x over previous
#include <cuda_runtime.h>
#include <cuda_bf16.h>
typedef unsigned u32; typedef unsigned long long u64; typedef unsigned short u16;
#define NBLK 128
#define NTHR 256
#define TT 1024
#define HH 512

// h stored pre-split: separate bf16 hi and lo planes, [batch][k]
__device__ __align__(16) u16 g_h1h[2][128 * HH], g_h1l[2][128 * HH];
__device__ __align__(16) u16 g_h2h[128 * HH],    g_h2l[128 * HH];
__device__ float g_xt[TT * 128];
__device__ u32 g_cnt, g_epoch, g_dead;

// smem layout (bytes)
#define O_W1  0          // weight tile: hi 16x1024B, lo at +16384 (32KB per matrix)
#define O_H2  32768
#define O_I2  65536
#define O_STG 98304      // 2 slots x 32768 (hi 16KB + lo 16KB), rows 128B swizzled
#define O_G   163840     // gates exchange: 16 x 132 f32 = 8448
#define O_WX  172288
#define O_BB1 172352
#define O_BB2 172416
#define O_RED 172480     // 256 f32
#define SMEMSZ 173568

__device__ __forceinline__ float sigf(float v){ return __fdividef(1.f, 1.f + __expf(-v)); }
__device__ __forceinline__ u32 s2u(const void* p){ u32 a; asm("{.reg .u64 t;cvta.to.shared.u64 t,%1;cvt.u32.u64 %0,t;}":"=r"(a):"l"(p)); return a; }
__device__ __forceinline__ u32 ldcg32(const void* p){ u32 v; asm volatile("ld.global.cg.u32 %0,[%1];":"=r"(v):"l"(p)); return v; }
__device__ __forceinline__ float bfv(u32 b){ u16 s=(u16)b; __nv_bfloat16 h=*(__nv_bfloat16*)&s; return __bfloat162float(h); }
__device__ __forceinline__ u16 tob(float f){ __nv_bfloat16 h=__float2bfloat16(f); return *(u16*)&h; }
__device__ __forceinline__ void ldm4(u32* r, u32 a){
  asm volatile("ldmatrix.sync.aligned.m8n8.x4.shared.b16 {%0,%1,%2,%3},[%4];"
    :"=r"(r[0]),"=r"(r[1]),"=r"(r[2]),"=r"(r[3]):"r"(a)); }
__device__ __forceinline__ void mma16816(float* c, const u32* a, const u32* b){
  asm volatile("mma.sync.aligned.m16n8k16.row.col.f32.bf16.bf16.f32 "
    "{%0,%1,%2,%3},{%4,%5,%6,%7},{%8,%9},{%0,%1,%2,%3};"
    :"+f"(c[0]),"+f"(c[1]),"+f"(c[2]),"+f"(c[3])
    :"r"(a[0]),"r"(a[1]),"r"(a[2]),"r"(a[3]),"r"(b[0]),"r"(b[1])); }
__device__ __forceinline__ void cpa16(u32 dst, const void* src){
  asm volatile("cp.async.cg.shared.global [%0],[%1],16;"::"r"(dst),"l"(src)); }
#define CPA_COMMIT() asm volatile("cp.async.commit_group;":::"memory")
#define CPA_WAIT0()  asm volatile("cp.async.wait_group 0;":::"memory")

// grid barrier with deadlock poison (proven R11/R12)
__device__ __forceinline__ void gridbar(){
  __syncthreads();
  if(threadIdx.x==0){
    u32 dead; asm volatile("ld.relaxed.gpu.u32 %0,[%1];":"=r"(dead):"l"(&g_dead));
    if(!dead){
      u32 e; asm volatile("ld.acquire.gpu.u32 %0,[%1];":"=r"(e):"l"(&g_epoch));
      u32 r; asm volatile("atom.add.release.gpu.u32 %0,[%1],%2;":"=r"(r):"l"(&g_cnt),"r"(1u));
      if(r==NBLK-1){
        asm volatile("st.relaxed.gpu.u32 [%0],%1;"::"l"(&g_cnt),"r"(0u));
        asm volatile("red.release.gpu.add.u32 [%0],%1;"::"l"(&g_epoch),"r"(1u));
      } else {
        u32 c, it=0;
        do{
          asm volatile("ld.acquire.gpu.u32 %0,[%1];":"=r"(c):"l"(&g_epoch));
          if(c!=e) break;
          asm volatile("ld.relaxed.gpu.u32 %0,[%1];":"=r"(dead):"l"(&g_dead));
          if(dead) break;
          if(++it > 20000000u){ atomicExch(&g_dead,1u); break; }
        } while(1);
      }
    }
  }
  __syncthreads();
}

// issue cp.async copies for chunk c of (hiP, loP) -> swizzled stage slot
__device__ __forceinline__ void stage_issue(u32 stg, const u16* hiP, const u16* loP,
                                            int c, int tid){
#pragma unroll
  for(int i=0;i<8;i++){
    int u = tid + i*256;              // 0..2047
    int p = u>>10;                    // 0 = hi plane, 1 = lo plane
    int row = (u>>3)&127;
    int atom = u&7;
    const u16* src = (p ? loP : hiP) + row*HH + c*64 + atom*8;
    u32 dst = stg + (u32)(p*16384 + row*128 + (((atom ^ (row&7)))<<4));
    cpa16(dst, src);
  }
  CPA_COMMIT();
}

// one 64-k chunk: 4 kt x (A hi/lo ldm4 + B hi/lo ldm4(2 n-tiles) + 6 mma)
__device__ __forceinline__ void gemm_chunk(u32 smb, int wbase, u32 stg, int c,
                                           int lane, int warp, float C[2][4]){
  const int krow = lane&15, khalf = lane>>4;
  const int brow = warp*16 + ((lane>>4)<<3) + (lane&7);
  const int bk   = (lane>>3)&1;
#pragma unroll
  for(int kt=0;kt<4;kt++){
    int aatom = c*8 + kt*2 + khalf;
    u32 aa = smb + (u32)wbase + (u32)(krow*1024) + (u32)(((aatom^(krow&7)))<<4);
    u32 ah[4], al[4]; ldm4(ah,aa); ldm4(al,aa+16384);
    int batom = kt*2 + bk;
    u32 ba = stg + (u32)(brow*128) + (u32)(((batom^(brow&7)))<<4);
    u32 bh[4], bl[4]; ldm4(bh,ba); ldm4(bl,ba+16384);
    mma16816(C[0],ah,bh);   mma16816(C[0],ah,bl);   mma16816(C[0],al,bh);
    mma16816(C[1],ah,bh+2); mma16816(C[1],ah,bl+2); mma16816(C[1],al,bh+2);
  }
}
// full 512-k GEMM: cp.async double-buffer, 1 sync per chunk
__device__ __forceinline__ void gemm_full(u32 smb, const u16* hiP, const u16* loP, int wbase,
                                          float C[2][4], int tid, int lane, int warp){
  stage_issue(smb+O_STG, hiP, loP, 0, tid);
#pragma unroll 1
  for(int c=0;c<8;c++){
    CPA_WAIT0();
    __syncthreads();   // chunk c staged; all warps done with mma(c-1) -> slot (c+1)&1 free
    if(c<7) stage_issue(smb+O_STG+(u32)(((c+1)&1)*32768), hiP, loP, c+1, tid);
    gemm_chunk(smb, wbase, smb+O_STG+(u32)((c&1)*32768), c, lane, warp, C);
  }
}

__global__ void __launch_bounds__(NTHR,1)
lstm_mma(const float* __restrict__ x, const float* __restrict__ Wih1, const float* __restrict__ Whh1,
         const float* __restrict__ bih1, const float* __restrict__ bhh1,
         const float* __restrict__ Wih2, const float* __restrict__ Whh2,
         const float* __restrict__ bih2, const float* __restrict__ bhh2,
         const float* __restrict__ Wlin, const float* __restrict__ blin, float* __restrict__ out){
  extern __shared__ __align__(128) char sm[];
  const int tid=threadIdx.x, blk=blockIdx.x, warp=tid>>5, lane=tid&31;
  const u32 smb = s2u(sm);

  // x transpose (each block its 8 t-columns)
  for(int i=tid;i<1024;i+=NTHR){ int t=blk*8+(i>>7), b=i&127; g_xt[t*128+b]=x[b*TT+t]; }
  // weights -> smem bf16 hi/lo, 1024B rows, swizzled atoms
  { const float* WS[3]={Whh1,Whh2,Wih2}; const int WO[3]={O_W1,O_H2,O_I2};
    for(int m=0;m<3;m++) for(int idx=tid; idx<16*HH; idx+=NTHR){
      int s=idx&15, k=idx>>4; int r=(s&3)*HH + blk*4 + (s>>2);
      float w=WS[m][r*HH+k]; u16 hb=tob(w); u16 lb=tob(w-bfv(hb));
      u32 off=(u32)(s*1024) + (u32)((((k>>3)^(s&7))<<4)) + (u32)((k&7)*2);
      *(u16*)(sm+WO[m]+off)=hb; *(u16*)(sm+WO[m]+16384+off)=lb; } }
  if(tid<16){ int s=tid, r=(s&3)*HH + blk*4 + (s>>2);
    ((float*)(sm+O_WX))[s]=Wih1[r];
    ((float*)(sm+O_BB1))[s]=bih1[r]+bhh1[r];
    ((float*)(sm+O_BB2))[s]=bih2[r]+bhh2[r]; }
  const float wl0=Wlin[tid*2], wl1=Wlin[tid*2+1], blinv=blin[0];
  for(int i=tid;i<512;i+=NTHR){ int b=i>>2, c=i&3; int o=b*HH+blk*4+c;
    g_h1h[0][o]=0; g_h1l[0][o]=0; g_h2h[o]=0; g_h2l[o]=0; }
  __syncthreads();
  gridbar();

  float c1s[4]={0,0,0,0}, c2s[4]={0,0,0,0};   // cells: threads 0-127, batch=tid, 4 cols

  for(int t=0;t<TT;t++){
    const u16* h1rh = g_h1h[t&1];      const u16* h1rl = g_h1l[t&1];
    u16* h1wh = g_h1h[(t&1)^1];        u16* h1wl = g_h1l[(t&1)^1];

    // out[t-1] partials (h2 stable since last gridbar)
    if(t>0){
      u32 ph=ldcg32((const char*)g_h2h + blk*1024 + tid*4);
      u32 pl=ldcg32((const char*)g_h2l + blk*1024 + tid*4);
      ((float*)(sm+O_RED))[tid]=(bfv(ph)+bfv(pl))*wl0+(bfv(ph>>16)+bfv(pl>>16))*wl1;
    }

    float C1[2][4]={{0,0,0,0},{0,0,0,0}}, C2[2][4]={{0,0,0,0},{0,0,0,0}};
    gemm_full(smb, h1rh, h1rl, O_W1, C1, tid, lane, warp);   // gates1 = Whh1*h1
    gemm_full(smb, g_h2h, g_h2l, O_H2, C2, tid, lane, warp); // gates2  = Whh2*h2

    // epilogue A: exchange C1 -> G
    { float* G=(float*)(sm+O_G);
#pragma unroll
      for(int nt=0;nt<2;nt++){ int n0=warp*16+nt*8+(lane&3)*2; int rr=lane>>2;
        *(float2*)&G[rr*132+n0]     = make_float2(C1[nt][0],C1[nt][1]);
        *(float2*)&G[(rr+8)*132+n0] = make_float2(C1[nt][2],C1[nt][3]); } }
    __syncthreads();
    if(t>0 && warp==7){ float* R=(float*)(sm+O_RED); float sv=0.f;
#pragma unroll
      for(int j=0;j<8;j++) sv+=R[lane+j*32];
      for(int o=16;o;o>>=1) sv+=__shfl_down_sync(~0u,sv,o);
      if(lane==0) out[blk*TT+t-1]=sv+blinv; }
    if(tid<128){
      float* G=(float*)(sm+O_G); float* WX=(float*)(sm+O_WX); float* B1=(float*)(sm+O_BB1);
      int b=tid; float xv=g_xt[t*128+b];
      u16 hh[4], hl[4];
#pragma unroll
      for(int cl=0;cl<4;cl++){ int s0=cl*4;
        float gi=G[(s0+0)*132+b]+B1[s0+0]+xv*WX[s0+0];
        float gf=G[(s0+1)*132+b]+B1[s0+1]+xv*WX[s0+1];
        float gg=G[(s0+2)*132+b]+B1[s0+2]+xv*WX[s0+2];
        float go=G[(s0+3)*132+b]+B1[s0+3]+xv*WX[s0+3];
        float cn=sigf(gf)*c1s[cl]+sigf(gi)*tanhf(gg); c1s[cl]=cn;
        float h=sigf(go)*tanhf(cn);
        hh[cl]=tob(h); hl[cl]=tob(h-bfv(hh[cl])); }
      *(ushort4*)&h1wh[b*HH+blk*4]=make_ushort4(hh[0],hh[1],hh[2],hh[3]);
      *(ushort4*)&h1wl[b*HH+blk*4]=make_ushort4(hl[0],hl[1],hl[2],hl[3]);
    }
    gridbar();   // h1[t] visible everywhere

    // phase B: gates2 += Wih2 * h1_new
    gemm_full(smb, h1wh, h1wl, O_I2, C2, tid, lane, warp);

    { float* G=(float*)(sm+O_G);
#pragma unroll
      for(int nt=0;nt<2;nt++){ int n0=warp*16+nt*8+(lane&3)*2; int rr=lane>>2;
        *(float2*)&G[rr*132+n0]     = make_float2(C2[nt][0],C2[nt][1]);
        *(float2*)&G[(rr+8)*132+n0] = make_float2(C2[nt][2],C2[nt][3]); } }
    __syncthreads();
    if(tid<128){
      float* G=(float*)(sm+O_G); float* B2=(float*)(sm+O_BB2);
      int b=tid;
      u16 hh[4], hl[4];
#pragma unroll
      for(int cl=0;cl<4;cl++){ int s0=cl*4;
        float gi=G[(s0+0)*132+b]+B2[s0+0];
        float gf=G[(s0+1)*132+b]+B2[s0+1];
        float gg=G[(s0+2)*132+b]+B2[s0+2];
        float go=G[(s0+3)*132+b]+B2[s0+3];
        float cn=sigf(gf)*c2s[cl]+sigf(gi)*tanhf(gg); c2s[cl]=cn;
        float h=sigf(go)*tanhf(cn);
        hh[cl]=tob(h); hl[cl]=tob(h-bfv(hh[cl])); }
      *(ushort4*)&g_h2h[b*HH+blk*4]=make_ushort4(hh[0],hh[1],hh[2],hh[3]);
      *(ushort4*)&g_h2l[b*HH+blk*4]=make_ushort4(hl[0],hl[1],hl[2],hl[3]);
    }
    gridbar();   // h2[t] visible everywhere
  }

  // final out column
  { u32 ph=ldcg32((const char*)g_h2h + blk*1024 + tid*4);
    u32 pl=ldcg32((const char*)g_h2l + blk*1024 + tid*4);
    ((float*)(sm+O_RED))[tid]=(bfv(ph)+bfv(pl))*wl0+(bfv(ph>>16)+bfv(pl>>16))*wl1;
    __syncthreads();
    if(warp==0){ float* R=(float*)(sm+O_RED); float sv=0.f;
#pragma unroll
      for(int j=0;j<8;j++) sv+=R[lane+j*32];
      for(int o=16;o;o>>=1) sv+=__shfl_down_sync(~0u,sv,o);
      if(lane==0) out[blk*TT+TT-1]=sv+blinv; } }
}

extern "C" void kernel_launch(void* const* d_in, const int* in_sizes, int n_in,
                              void* d_out, int out_size){
  const float* x   =(const float*)d_in[0];
  const float* Wih1=(const float*)d_in[1];
  const float* Whh1=(const float*)d_in[2];
  const float* bih1=(const float*)d_in[3];
  const float* bhh1=(const float*)d_in[4];
  const float* Wih2=(const float*)d_in[5];
  const float* Whh2=(const float*)d_in[6];
  const float* bih2=(const float*)d_in[7];
  const float* bhh2=(const float*)d_in[8];
  const float* Wlin=(const float*)d_in[9];
  const float* blin=(const float*)d_in[10];
  float* out=(float*)d_out;
  cudaFuncSetAttribute(lstm_mma, cudaFuncAttributeMaxDynamicSharedMemorySize, SMEMSZ);
  lstm_mma<<<NBLK,NTHR,SMEMSZ>>>(x,Wih1,Whh1,bih1,bhh1,Wih2,Whh2,bih2,bhh2,Wlin,blin,out);
}